// round 13
// baseline (speedup 1.0000x reference)
#include <cuda_runtime.h>
#include <cuda_fp16.h>
#include <cstdint>

#define NU 100000
#define NI 50000
#define EE 500000
#define C  128
#define LL 2
#define BB 1024

#define NBLK_I ((NI + 255) / 256)   // 196
#define NBLK_U ((NU + 255) / 256)   // 391

// ---------------- static device scratch ----------------
__device__ float g_xu_a[NU * C];
__device__ float g_xu_b[NU * C];
__device__ float g_xi_a[NI * C];
__device__ float g_xi_b[NI * C];
__device__ float g_agg_u[NU * C];
__device__ float g_agg_i[NI * C];
// fragment-ordered fp16 split weights: [lt(4)][k16(16)][ntile(16)][lane(32)] uint4=(bh0,bh1,bl0,bl1)
__device__ __align__(16) uint4 g_wfrag[4 * 16 * 16 * 32];

// ---------------- helpers ----------------
__device__ __forceinline__ uint32_t h2u(half2 h) { return *reinterpret_cast<uint32_t*>(&h); }
__device__ __forceinline__ void split16(float x, half& h, half& l) {
    h = __float2half_rn(x);
    l = __float2half_rn(x - __half2float(h));
}
// packed split (bit-identical rn rounding)
__device__ __forceinline__ void split2(float2 v, uint32_t& hi, uint32_t& lo) {
    half2 h = __float22half2_rn(v);
    float2 hf = __half22float2(h);
    half2 l = __float22half2_rn(make_float2(v.x - hf.x, v.y - hf.y));
    hi = h2u(h);
    lo = h2u(l);
}
__device__ __forceinline__ void mma16(float* c, uint32_t a0, uint32_t a1, uint32_t a2, uint32_t a3,
                                      uint32_t b0, uint32_t b1) {
    asm("mma.sync.aligned.m16n8k16.row.col.f32.f16.f16.f32 "
        "{%0,%1,%2,%3},{%4,%5,%6,%7},{%8,%9},{%0,%1,%2,%3};"
        : "+f"(c[0]), "+f"(c[1]), "+f"(c[2]), "+f"(c[3])
        : "r"(a0), "r"(a1), "r"(a2), "r"(a3), "r"(b0), "r"(b1));
}
__device__ __forceinline__ uint32_t smem_u32(const void* p) {
    uint32_t a;
    asm("{ .reg .u64 t; cvta.to.shared.u64 t, %1; cvt.u32.u64 %0, t; }" : "=r"(a) : "l"(p));
    return a;
}
#define CP_ASYNC16(dst_u32, src_ptr) \
    asm volatile("cp.async.cg.shared.global [%0], [%1], 16;" :: "r"(dst_u32), "l"(src_ptr) : "memory")
#define CP_COMMIT() asm volatile("cp.async.commit_group;" ::: "memory")
#define CP_WAIT(n)  asm volatile("cp.async.wait_group %0;" :: "n"(n) : "memory")

// ---------------- edge scatter-add: 8 edges per warp (MLP=8) ----------------
__global__ void scatter_kernel(const float* __restrict__ x, const int* __restrict__ src,
                               const int* __restrict__ dst, float* __restrict__ agg, int E) {
    int gid = blockIdx.x * blockDim.x + threadIdx.x;
    int w = gid >> 5;
    int lane = gid & 31;
    int e0 = w * 8;
    if (e0 >= E) return;
    int4 sa = *reinterpret_cast<const int4*>(src + e0);
    int4 sb = *reinterpret_cast<const int4*>(src + e0 + 4);
    int4 da = *reinterpret_cast<const int4*>(dst + e0);
    int4 db = *reinterpret_cast<const int4*>(dst + e0 + 4);
    float4 v0 = __ldg(reinterpret_cast<const float4*>(x + (size_t)sa.x * C) + lane);
    float4 v1 = __ldg(reinterpret_cast<const float4*>(x + (size_t)sa.y * C) + lane);
    float4 v2 = __ldg(reinterpret_cast<const float4*>(x + (size_t)sa.z * C) + lane);
    float4 v3 = __ldg(reinterpret_cast<const float4*>(x + (size_t)sa.w * C) + lane);
    float4 v4 = __ldg(reinterpret_cast<const float4*>(x + (size_t)sb.x * C) + lane);
    float4 v5 = __ldg(reinterpret_cast<const float4*>(x + (size_t)sb.y * C) + lane);
    float4 v6 = __ldg(reinterpret_cast<const float4*>(x + (size_t)sb.z * C) + lane);
    float4 v7 = __ldg(reinterpret_cast<const float4*>(x + (size_t)sb.w * C) + lane);
#define RED4(dptr, v) \
    asm volatile("red.global.add.v4.f32 [%0], {%1, %2, %3, %4};" \
                 :: "l"(dptr), "f"((v).x), "f"((v).y), "f"((v).z), "f"((v).w) : "memory")
    RED4(agg + (size_t)da.x * C + lane * 4, v0);
    RED4(agg + (size_t)da.y * C + lane * 4, v1);
    RED4(agg + (size_t)da.z * C + lane * 4, v2);
    RED4(agg + (size_t)da.w * C + lane * 4, v3);
    RED4(agg + (size_t)db.x * C + lane * 4, v4);
    RED4(agg + (size_t)db.y * C + lane * 4, v5);
    RED4(agg + (size_t)db.z * C + lane * 4, v6);
    RED4(agg + (size_t)db.w * C + lane * 4, v7);
#undef RED4
}

// ---------------- weight prep: fp16 hi/lo split into per-lane fragment order ----------------
__global__ void prep_w(const float* __restrict__ wrel, const float* __restrict__ wroot,
                       uint4* __restrict__ outw) {
    int gid = blockIdx.x * blockDim.x + threadIdx.x;   // [lt][k16][nt][lane]
    if (gid >= 4 * 16 * 16 * 32) return;
    int lane = gid & 31;
    int nt   = (gid >> 5) & 15;
    int k16  = (gid >> 9) & 15;
    int lt   = gid >> 13;
    int n  = nt * 8 + (lane >> 2);
    int k0 = k16 * 16 + (lane & 3) * 2;
    float w[4];
#pragma unroll
    for (int j = 0; j < 4; ++j) {
        int k = k0 + (j >> 1) * 8 + (j & 1);
        w[j] = (k < 128) ? wrel[((size_t)lt * 128 + k) * 128 + n]
                         : wroot[((size_t)lt * 128 + (k - 128)) * 128 + n];
    }
    half h[4], l[4];
#pragma unroll
    for (int j = 0; j < 4; ++j) split16(w[j], h[j], l[j]);
    outw[gid] = make_uint4(h2u(__halves2half2(h[0], h[1])), h2u(__halves2half2(h[2], h[3])),
                           h2u(__halves2half2(l[0], l[1])), h2u(__halves2half2(l[2], l[3])));
}

// ---------------- fused fp16 mma.sync GEMM + bias + LN + ReLU + agg re-zero ----------------
// 1024 threads / 32 warps, warp tile 32x32 -> 8 warps/SMSP (2x round-11).
// Weights staged in smem (128KB); A via cp.async triple buffer. Numerics unchanged.
#define W_SMEM_U4 (16 * 16 * 32)                  // 8192 uint4 = 128KB
#define AS_STRIDE 20
#define ABUF_F (256 * AS_STRIDE)                  // 5120 floats per buffer
#define SM_ABASE 32768                            // float offset of A buffers
#define O_STRIDE 132
#define GEMM_SMEM_BYTES ((SM_ABASE + 3 * ABUF_F) * 4)   // 192512

__global__ void __launch_bounds__(1024, 1) gemm_tc(
    const float* __restrict__ agg, const float* __restrict__ xin,
    float* aggz,                              // same buffer as agg, zeroed in epilogue
    const uint4* __restrict__ wfrag,
    const float* __restrict__ bias, const float* __restrict__ gln, const float* __restrict__ blnv,
    float* __restrict__ out, int M)
{
    extern __shared__ float smem[];
    uint4* sw = reinterpret_cast<uint4*>(smem);
    const int tid  = threadIdx.x;
    const int lane = tid & 31;
    const int wid  = tid >> 5;        // 0..31
    const int wm   = wid >> 2;        // 0..7  (32-row group)
    const int wn   = wid & 3;         // 0..3  (32-col group)
    const int row0 = blockIdx.x * 256;

    // ---- copy-lane coords: thread copies 16B (4 floats) per stage ----
    const int crow = tid >> 2;        // 0..255
    const int cq   = tid & 3;         // 0..3
    int gcr = row0 + crow; if (gcr > M - 1) gcr = M - 1;
    const size_t csrc_off = (size_t)gcr * C + cq * 4;
    const uint32_t abase = smem_u32(smem + SM_ABASE) + (crow * AS_STRIDE + cq * 4) * 4;

#define ISSUE(st) do {                                                              \
        const float* sp = (((st) < 8) ? agg : xin) + csrc_off + ((st) & 7) * 16;    \
        CP_ASYNC16(abase + ((st) % 3) * (ABUF_F * 4), sp);                          \
        CP_COMMIT();                                                                \
    } while (0)

    ISSUE(0);
    ISSUE(1);

    // ---- stage all weight fragments for this layer-type into smem ----
#pragma unroll
    for (int i = 0; i < W_SMEM_U4 / 1024; ++i)
        sw[i * 1024 + tid] = __ldg(wfrag + i * 1024 + tid);

    const int kq = 2 * (lane & 3);

    float c[2][4][4];
#pragma unroll
    for (int nt = 0; nt < 4; ++nt) {
        int col = wn * 32 + nt * 8 + kq;
        float b0 = __ldg(bias + col), b1 = __ldg(bias + col + 1);
#pragma unroll
        for (int mt = 0; mt < 2; ++mt) {
            c[mt][nt][0] = b0; c[mt][nt][1] = b1;
            c[mt][nt][2] = b0; c[mt][nt][3] = b1;
        }
    }
    __syncthreads();   // weights staged

    // ---- pipelined mainloop ----
#pragma unroll
    for (int s = 0; s < 16; ++s) {
        if (s == 15) CP_WAIT(0); else CP_WAIT(1);
        __syncthreads();
        if (s + 2 < 16) ISSUE(s + 2);

        const float* ab = smem + SM_ABASE + (s % 3) * ABUF_F;
        uint32_t ah[2][4], al[2][4];
#pragma unroll
        for (int mt = 0; mt < 2; ++mt) {
            const int rb = wm * 32 + mt * 16 + (lane >> 2);
            float2 f0 = *reinterpret_cast<const float2*>(ab + rb * AS_STRIDE + kq);
            float2 f1 = *reinterpret_cast<const float2*>(ab + (rb + 8) * AS_STRIDE + kq);
            float2 f2 = *reinterpret_cast<const float2*>(ab + rb * AS_STRIDE + kq + 8);
            float2 f3 = *reinterpret_cast<const float2*>(ab + (rb + 8) * AS_STRIDE + kq + 8);
            split2(f0, ah[mt][0], al[mt][0]);
            split2(f1, ah[mt][1], al[mt][1]);
            split2(f2, ah[mt][2], al[mt][2]);
            split2(f3, ah[mt][3], al[mt][3]);
        }
        const uint4* wp = sw + ((size_t)s * 16 + wn * 4) * 32 + lane;
#pragma unroll
        for (int nt = 0; nt < 4; ++nt) {
            uint4 bf = wp[nt * 32];
#pragma unroll
            for (int mt = 0; mt < 2; ++mt) {
                mma16(c[mt][nt], ah[mt][0], ah[mt][1], ah[mt][2], ah[mt][3], bf.x, bf.y); // hi*hi
                mma16(c[mt][nt], al[mt][0], al[mt][1], al[mt][2], al[mt][3], bf.x, bf.y); // lo*hi
                mma16(c[mt][nt], ah[mt][0], ah[mt][1], ah[mt][2], ah[mt][3], bf.z, bf.w); // hi*lo
            }
        }
    }
#undef ISSUE

    __syncthreads();   // all LDS reads done; smem now reusable as sOut

    // ---- stage C to smem ----
#pragma unroll
    for (int mt = 0; mt < 2; ++mt) {
        int r = wm * 32 + mt * 16 + (lane >> 2);
#pragma unroll
        for (int nt = 0; nt < 4; ++nt) {
            int col = wn * 32 + nt * 8 + kq;
            *reinterpret_cast<float2*>(smem + (size_t)r * O_STRIDE + col)       = make_float2(c[mt][nt][0], c[mt][nt][1]);
            *reinterpret_cast<float2*>(smem + (size_t)(r + 8) * O_STRIDE + col) = make_float2(c[mt][nt][2], c[mt][nt][3]);
        }
    }
    __syncthreads();

    // ---- LN + ReLU + store + agg re-zero: warp per row (8 rows/warp) ----
    const int cb = lane * 4;
    const float4 z4 = make_float4(0.f, 0.f, 0.f, 0.f);
    float4 g4 = __ldg(reinterpret_cast<const float4*>(gln + cb));
    float4 b4 = __ldg(reinterpret_cast<const float4*>(blnv + cb));
#pragma unroll 4
    for (int it = 0; it < 8; ++it) {
        int r = wid * 8 + it;
        float4 v = *reinterpret_cast<const float4*>(smem + (size_t)r * O_STRIDE + cb);
        float sum = v.x + v.y + v.z + v.w;
        float ss  = v.x * v.x + v.y * v.y + v.z * v.z + v.w * v.w;
#pragma unroll
        for (int o = 16; o > 0; o >>= 1) {
            sum += __shfl_xor_sync(0xffffffffu, sum, o);
            ss  += __shfl_xor_sync(0xffffffffu, ss, o);
        }
        float mu = sum * (1.f / 128.f);
        float rstd = rsqrtf(fmaxf(ss * (1.f / 128.f) - mu * mu, 0.f) + 1e-5f);
        int gr = row0 + r;
        if (gr < M) {
            float o0 = fmaxf(fmaf((v.x - mu) * rstd, g4.x, b4.x), 0.f);
            float o1 = fmaxf(fmaf((v.y - mu) * rstd, g4.y, b4.y), 0.f);
            float o2 = fmaxf(fmaf((v.z - mu) * rstd, g4.z, b4.z), 0.f);
            float o3 = fmaxf(fmaf((v.w - mu) * rstd, g4.w, b4.w), 0.f);
            *reinterpret_cast<float4*>(out + (size_t)gr * C + cb) = make_float4(o0, o1, o2, o3);
            *reinterpret_cast<float4*>(aggz + (size_t)gr * C + cb) = z4;   // ready for next scatter
        }
    }
}

// ---------------- head ----------------
__global__ void head_kernel(const float* __restrict__ xu, const float* __restrict__ w,
                            const float* __restrict__ b, float* __restrict__ out) {
    int gid = blockIdx.x * blockDim.x + threadIdx.x;
    int wd = gid >> 5, lane = gid & 31;
    if (wd >= BB) return;
    float4 v  = *reinterpret_cast<const float4*>(xu + (size_t)wd * C + lane * 4);
    float4 ww = *reinterpret_cast<const float4*>(w + lane * 4);
    float s = v.x * ww.x + v.y * ww.y + v.z * ww.z + v.w * ww.w;
#pragma unroll
    for (int o = 16; o > 0; o >>= 1) s += __shfl_xor_sync(0xffffffffu, s, o);
    if (lane == 0) out[wd] = s + b[0];
}

// ---------------- launch: two-stream pipelined item/user chains ----------------
extern "C" void kernel_launch(void* const* d_in, const int* in_sizes, int n_in,
                              void* d_out, int out_size) {
    const float* x_user  = (const float*)d_in[0];
    const float* x_item  = (const float*)d_in[1];
    const int* e_ui_src  = (const int*)d_in[2];
    const int* e_ui_dst  = (const int*)d_in[3];
    const int* e_iu_src  = (const int*)d_in[4];
    const int* e_iu_dst  = (const int*)d_in[5];
    const float* w_rel   = (const float*)d_in[6];   // [L,2,C,C]
    const float* w_root  = (const float*)d_in[7];
    const float* bias    = (const float*)d_in[8];   // [L,2,C]
    const float* ln_g    = (const float*)d_in[9];
    const float* ln_b    = (const float*)d_in[10];
    const float* lin_w   = (const float*)d_in[11];
    const float* lin_b   = (const float*)d_in[12];
    float* out = (float*)d_out;

    float *xu_a, *xu_b, *xi_a, *xi_b, *aggu, *aggi;
    uint4* wfrag;
    cudaGetSymbolAddress((void**)&xu_a, g_xu_a);
    cudaGetSymbolAddress((void**)&xu_b, g_xu_b);
    cudaGetSymbolAddress((void**)&xi_a, g_xi_a);
    cudaGetSymbolAddress((void**)&xi_b, g_xi_b);
    cudaGetSymbolAddress((void**)&aggu, g_agg_u);
    cudaGetSymbolAddress((void**)&aggi, g_agg_i);
    cudaGetSymbolAddress((void**)&wfrag, g_wfrag);

    cudaFuncSetAttribute(gemm_tc, cudaFuncAttributeMaxDynamicSharedMemorySize, GEMM_SMEM_BYTES);

    cudaStream_t sB = 0;
    cudaEvent_t evFork = 0, evI0 = 0, evU0 = 0, evU1 = 0;
    bool multi = (cudaStreamCreateWithFlags(&sB, cudaStreamNonBlocking) == cudaSuccess);
    if (multi) multi =
        (cudaEventCreateWithFlags(&evFork, cudaEventDisableTiming) == cudaSuccess) &&
        (cudaEventCreateWithFlags(&evI0,   cudaEventDisableTiming) == cudaSuccess) &&
        (cudaEventCreateWithFlags(&evU0,   cudaEventDisableTiming) == cudaSuccess) &&
        (cudaEventCreateWithFlags(&evU1,   cudaEventDisableTiming) == cudaSuccess);
    cudaStream_t sU = multi ? sB : (cudaStream_t)0;   // user-chain stream

    const int SBLK = ((EE / 8) * 32 + 255) / 256;

    prep_w<<<(4 * 16 * 16 * 32 + 255) / 256, 256>>>(w_rel, w_root, wfrag);
    if (multi) {
        cudaEventRecord(evFork, 0);
        cudaStreamWaitEvent(sU, evFork, 0);
    }

    // ---- layer 0 ----
    scatter_kernel<<<SBLK, 256, 0, 0>>>(x_user, e_ui_src, e_ui_dst, aggi, EE);
    scatter_kernel<<<SBLK, 256, 0, sU>>>(x_item, e_iu_src, e_iu_dst, aggu, EE);
    gemm_tc<<<NBLK_I, 1024, GEMM_SMEM_BYTES, 0>>>(
        aggi, x_item, aggi, wfrag + (size_t)0 * 16 * 16 * 32,
        bias + 0 * C, ln_g + 1 * C, ln_b + 1 * C, xi_a, NI);
    if (multi) cudaEventRecord(evI0, 0);
    gemm_tc<<<NBLK_U, 1024, GEMM_SMEM_BYTES, sU>>>(
        aggu, x_user, aggu, wfrag + (size_t)1 * 16 * 16 * 32,
        bias + 1 * C, ln_g + 0 * C, ln_b + 0 * C, xu_a, NU);
    if (multi) cudaEventRecord(evU0, sU);

    // ---- layer 1 ----
    if (multi) cudaStreamWaitEvent(0, evU0, 0);       // scatter_ui(1) reads xu_a
    scatter_kernel<<<SBLK, 256, 0, 0>>>(xu_a, e_ui_src, e_ui_dst, aggi, EE);
    if (multi) cudaStreamWaitEvent(sU, evI0, 0);      // scatter_iu(1) reads xi_a
    scatter_kernel<<<SBLK, 256, 0, sU>>>(xi_a, e_iu_src, e_iu_dst, aggu, EE);
    gemm_tc<<<NBLK_I, 1024, GEMM_SMEM_BYTES, 0>>>(
        aggi, xi_a, aggi, wfrag + (size_t)2 * 16 * 16 * 32,
        bias + 2 * C, ln_g + 3 * C, ln_b + 3 * C, xi_b, NI);
    gemm_tc<<<NBLK_U, 1024, GEMM_SMEM_BYTES, sU>>>(
        aggu, xu_a, aggu, wfrag + (size_t)3 * 16 * 16 * 32,
        bias + 3 * C, ln_g + 2 * C, ln_b + 2 * C, xu_b, NU);
    if (multi) {
        cudaEventRecord(evU1, sU);
        cudaStreamWaitEvent(0, evU1, 0);              // join user chain back
    }

    head_kernel<<<(BB * 32 + 255) / 256, 256, 0, 0>>>(xu_b, lin_w, lin_b, out);
}

// round 14
// speedup vs baseline: 3.1121x; 3.1121x over previous
#include <cuda_runtime.h>
#include <cuda_fp16.h>
#include <cstdint>

#define NU 100000
#define NI 50000
#define EE 500000
#define C  128
#define LL 2
#define BB 1024

#define NBLK_I ((NI + 255) / 256)   // 196
#define NBLK_H ((BB + 255) / 256)   // 4 (head-relevant user rows)

// ---------------- static device scratch ----------------
__device__ float g_xu_a[NU * C];
__device__ float g_xu_b[NU * C];
__device__ float g_xi_a[NI * C];
__device__ float g_agg_u[NU * C];
__device__ float g_agg_i[NI * C];
// fragment-ordered fp16 split weights: [lt(4)][k16(16)][ntile(16)][lane(32)] uint4=(bh0,bh1,bl0,bl1)
__device__ __align__(16) uint4 g_wfrag[4 * 16 * 16 * 32];

// ---------------- helpers ----------------
__device__ __forceinline__ uint32_t h2u(half2 h) { return *reinterpret_cast<uint32_t*>(&h); }
__device__ __forceinline__ void split16(float x, half& h, half& l) {
    h = __float2half_rn(x);
    l = __float2half_rn(x - __half2float(h));
}
__device__ __forceinline__ void split2(float2 v, uint32_t& hi, uint32_t& lo) {
    half2 h = __float22half2_rn(v);
    float2 hf = __half22float2(h);
    half2 l = __float22half2_rn(make_float2(v.x - hf.x, v.y - hf.y));
    hi = h2u(h);
    lo = h2u(l);
}
__device__ __forceinline__ void mma16(float* c, uint32_t a0, uint32_t a1, uint32_t a2, uint32_t a3,
                                      uint32_t b0, uint32_t b1) {
    asm("mma.sync.aligned.m16n8k16.row.col.f32.f16.f16.f32 "
        "{%0,%1,%2,%3},{%4,%5,%6,%7},{%8,%9},{%0,%1,%2,%3};"
        : "+f"(c[0]), "+f"(c[1]), "+f"(c[2]), "+f"(c[3])
        : "r"(a0), "r"(a1), "r"(a2), "r"(a3), "r"(b0), "r"(b1));
}
__device__ __forceinline__ uint32_t smem_u32(const void* p) {
    uint32_t a;
    asm("{ .reg .u64 t; cvta.to.shared.u64 t, %1; cvt.u32.u64 %0, t; }" : "=r"(a) : "l"(p));
    return a;
}
#define CP_ASYNC16(dst_u32, src_ptr) \
    asm volatile("cp.async.cg.shared.global [%0], [%1], 16;" :: "r"(dst_u32), "l"(src_ptr) : "memory")
#define CP_COMMIT() asm volatile("cp.async.commit_group;" ::: "memory")
#define CP_WAIT(n)  asm volatile("cp.async.wait_group %0;" :: "n"(n) : "memory")

#define RED4(dptr, v) \
    asm volatile("red.global.add.v4.f32 [%0], {%1, %2, %3, %4};" \
                 :: "l"(dptr), "f"((v).x), "f"((v).y), "f"((v).z), "f"((v).w) : "memory")

// ---------------- full edge scatter-add: 8 edges per warp (MLP=8) ----------------
__global__ void scatter_kernel(const float* __restrict__ x, const int* __restrict__ src,
                               const int* __restrict__ dst, float* __restrict__ agg, int E) {
    int gid = blockIdx.x * blockDim.x + threadIdx.x;
    int w = gid >> 5;
    int lane = gid & 31;
    int e0 = w * 8;
    if (e0 >= E) return;
    int4 sa = *reinterpret_cast<const int4*>(src + e0);
    int4 sb = *reinterpret_cast<const int4*>(src + e0 + 4);
    int4 da = *reinterpret_cast<const int4*>(dst + e0);
    int4 db = *reinterpret_cast<const int4*>(dst + e0 + 4);
    float4 v0 = __ldg(reinterpret_cast<const float4*>(x + (size_t)sa.x * C) + lane);
    float4 v1 = __ldg(reinterpret_cast<const float4*>(x + (size_t)sa.y * C) + lane);
    float4 v2 = __ldg(reinterpret_cast<const float4*>(x + (size_t)sa.z * C) + lane);
    float4 v3 = __ldg(reinterpret_cast<const float4*>(x + (size_t)sa.w * C) + lane);
    float4 v4 = __ldg(reinterpret_cast<const float4*>(x + (size_t)sb.x * C) + lane);
    float4 v5 = __ldg(reinterpret_cast<const float4*>(x + (size_t)sb.y * C) + lane);
    float4 v6 = __ldg(reinterpret_cast<const float4*>(x + (size_t)sb.z * C) + lane);
    float4 v7 = __ldg(reinterpret_cast<const float4*>(x + (size_t)sb.w * C) + lane);
    RED4(agg + (size_t)da.x * C + lane * 4, v0);
    RED4(agg + (size_t)da.y * C + lane * 4, v1);
    RED4(agg + (size_t)da.z * C + lane * 4, v2);
    RED4(agg + (size_t)da.w * C + lane * 4, v3);
    RED4(agg + (size_t)db.x * C + lane * 4, v4);
    RED4(agg + (size_t)db.y * C + lane * 4, v5);
    RED4(agg + (size_t)db.z * C + lane * 4, v6);
    RED4(agg + (size_t)db.w * C + lane * 4, v7);
}

// ---------------- filtered scatter: only edges with dst < BB contribute ----------------
// (~1% of edges pass; cost is dominated by scanning the dst array)
__global__ void scatter_filt_kernel(const float* __restrict__ x, const int* __restrict__ src,
                                    const int* __restrict__ dst, float* __restrict__ agg, int E) {
    int gid = blockIdx.x * blockDim.x + threadIdx.x;
    int w = gid >> 5;
    int lane = gid & 31;
    int e0 = w * 16;
    if (e0 >= E) return;
    int d[16];
    *reinterpret_cast<int4*>(d)      = *reinterpret_cast<const int4*>(dst + e0);
    *reinterpret_cast<int4*>(d + 4)  = *reinterpret_cast<const int4*>(dst + e0 + 4);
    *reinterpret_cast<int4*>(d + 8)  = *reinterpret_cast<const int4*>(dst + e0 + 8);
    *reinterpret_cast<int4*>(d + 12) = *reinterpret_cast<const int4*>(dst + e0 + 12);
#pragma unroll
    for (int j = 0; j < 16; ++j) {
        if (d[j] < BB) {
            int s = __ldg(src + e0 + j);
            float4 v = __ldg(reinterpret_cast<const float4*>(x + (size_t)s * C) + lane);
            RED4(agg + (size_t)d[j] * C + lane * 4, v);
        }
    }
}

// ---------------- weight prep: fp16 hi/lo split into per-lane fragment order ----------------
__global__ void prep_w(const float* __restrict__ wrel, const float* __restrict__ wroot,
                       uint4* __restrict__ outw) {
    int gid = blockIdx.x * blockDim.x + threadIdx.x;   // [lt][k16][nt][lane]
    if (gid >= 4 * 16 * 16 * 32) return;
    int lane = gid & 31;
    int nt   = (gid >> 5) & 15;
    int k16  = (gid >> 9) & 15;
    int lt   = gid >> 13;
    int n  = nt * 8 + (lane >> 2);
    int k0 = k16 * 16 + (lane & 3) * 2;
    float w[4];
#pragma unroll
    for (int j = 0; j < 4; ++j) {
        int k = k0 + (j >> 1) * 8 + (j & 1);
        w[j] = (k < 128) ? wrel[((size_t)lt * 128 + k) * 128 + n]
                         : wroot[((size_t)lt * 128 + (k - 128)) * 128 + n];
    }
    half h[4], l[4];
#pragma unroll
    for (int j = 0; j < 4; ++j) split16(w[j], h[j], l[j]);
    outw[gid] = make_uint4(h2u(__halves2half2(h[0], h[1])), h2u(__halves2half2(h[2], h[3])),
                           h2u(__halves2half2(l[0], l[1])), h2u(__halves2half2(l[2], l[3])));
}

// ---------------- fused fp16 mma.sync GEMM + bias + LN + ReLU + agg re-zero ----------------
// (round-11 version: 512 threads, weights in smem, cp.async A pipeline — best measured)
#define W_SMEM_U4 (16 * 16 * 32)                  // 8192 uint4 = 128KB
#define AS_STRIDE 20
#define ABUF_F (256 * AS_STRIDE)                  // 5120 floats per buffer
#define SM_ABASE 32768                            // float offset of A buffers
#define O_STRIDE 132
#define GEMM_SMEM_BYTES ((SM_ABASE + 3 * ABUF_F) * 4)   // 192512

__global__ void __launch_bounds__(512, 1) gemm_tc(
    const float* __restrict__ agg, const float* __restrict__ xin,
    float* aggz,                              // same buffer as agg, zeroed in epilogue
    const uint4* __restrict__ wfrag,
    const float* __restrict__ bias, const float* __restrict__ gln, const float* __restrict__ blnv,
    float* __restrict__ out, int M)
{
    extern __shared__ float smem[];
    uint4* sw = reinterpret_cast<uint4*>(smem);
    const int tid  = threadIdx.x;
    const int lane = tid & 31;
    const int wid  = tid >> 5;        // 0..15
    const int wm   = wid >> 1;        // 0..7
    const int wn   = wid & 1;         // 0..1
    const int row0 = blockIdx.x * 256;

    const int crow  = tid >> 1;       // 0..255
    const int chalf = tid & 1;        // 0/1
    int gcr = row0 + crow; if (gcr > M - 1) gcr = M - 1;
    const size_t csrc_off = (size_t)gcr * C + chalf * 8;
    uint32_t cdst[3];
#pragma unroll
    for (int b = 0; b < 3; ++b)
        cdst[b] = smem_u32(smem + SM_ABASE + b * ABUF_F + crow * AS_STRIDE + chalf * 8);

#define ISSUE(st) do {                                                              \
        const float* sp = (((st) < 8) ? agg : xin) + csrc_off + ((st) & 7) * 16;    \
        uint32_t d = cdst[(st) % 3];                                                \
        CP_ASYNC16(d, sp);                                                          \
        CP_ASYNC16(d + 16, sp + 4);                                                 \
        CP_COMMIT();                                                                \
    } while (0)

    ISSUE(0);
    ISSUE(1);

#pragma unroll
    for (int i = 0; i < W_SMEM_U4 / 512; ++i)
        sw[i * 512 + tid] = __ldg(wfrag + i * 512 + tid);

    const int kq = 2 * (lane & 3);

    float c[2][8][4];
#pragma unroll
    for (int nt = 0; nt < 8; ++nt) {
        int col = wn * 64 + nt * 8 + kq;
        float b0 = __ldg(bias + col), b1 = __ldg(bias + col + 1);
#pragma unroll
        for (int mt = 0; mt < 2; ++mt) {
            c[mt][nt][0] = b0; c[mt][nt][1] = b1;
            c[mt][nt][2] = b0; c[mt][nt][3] = b1;
        }
    }
    __syncthreads();   // weights staged

#pragma unroll
    for (int s = 0; s < 16; ++s) {
        if (s == 15) CP_WAIT(0); else CP_WAIT(1);
        __syncthreads();
        if (s + 2 < 16) ISSUE(s + 2);

        const float* ab = smem + SM_ABASE + (s % 3) * ABUF_F;
        uint32_t ah[2][4], al[2][4];
#pragma unroll
        for (int mt = 0; mt < 2; ++mt) {
            const int rb = wm * 32 + mt * 16 + (lane >> 2);
            float2 f0 = *reinterpret_cast<const float2*>(ab + rb * AS_STRIDE + kq);
            float2 f1 = *reinterpret_cast<const float2*>(ab + (rb + 8) * AS_STRIDE + kq);
            float2 f2 = *reinterpret_cast<const float2*>(ab + rb * AS_STRIDE + kq + 8);
            float2 f3 = *reinterpret_cast<const float2*>(ab + (rb + 8) * AS_STRIDE + kq + 8);
            split2(f0, ah[mt][0], al[mt][0]);
            split2(f1, ah[mt][1], al[mt][1]);
            split2(f2, ah[mt][2], al[mt][2]);
            split2(f3, ah[mt][3], al[mt][3]);
        }
        const uint4* wp = sw + ((size_t)s * 16 + wn * 8) * 32 + lane;
#pragma unroll
        for (int nt = 0; nt < 8; ++nt) {
            uint4 bf = wp[nt * 32];
#pragma unroll
            for (int mt = 0; mt < 2; ++mt) {
                mma16(c[mt][nt], ah[mt][0], ah[mt][1], ah[mt][2], ah[mt][3], bf.x, bf.y); // hi*hi
                mma16(c[mt][nt], al[mt][0], al[mt][1], al[mt][2], al[mt][3], bf.x, bf.y); // lo*hi
                mma16(c[mt][nt], ah[mt][0], ah[mt][1], ah[mt][2], ah[mt][3], bf.z, bf.w); // hi*lo
            }
        }
    }
#undef ISSUE

    __syncthreads();   // all LDS reads done; smem now reusable as sOut

#pragma unroll
    for (int mt = 0; mt < 2; ++mt) {
        int r = wm * 32 + mt * 16 + (lane >> 2);
#pragma unroll
        for (int nt = 0; nt < 8; ++nt) {
            int col = wn * 64 + nt * 8 + kq;
            *reinterpret_cast<float2*>(smem + (size_t)r * O_STRIDE + col)       = make_float2(c[mt][nt][0], c[mt][nt][1]);
            *reinterpret_cast<float2*>(smem + (size_t)(r + 8) * O_STRIDE + col) = make_float2(c[mt][nt][2], c[mt][nt][3]);
        }
    }
    __syncthreads();

    const int cb = lane * 4;
    const float4 z4 = make_float4(0.f, 0.f, 0.f, 0.f);
    float4 g4 = __ldg(reinterpret_cast<const float4*>(gln + cb));
    float4 b4 = __ldg(reinterpret_cast<const float4*>(blnv + cb));
#pragma unroll 4
    for (int it = 0; it < 16; ++it) {
        int r = wid * 16 + it;
        float4 v = *reinterpret_cast<const float4*>(smem + (size_t)r * O_STRIDE + cb);
        float sum = v.x + v.y + v.z + v.w;
        float ss  = v.x * v.x + v.y * v.y + v.z * v.z + v.w * v.w;
#pragma unroll
        for (int o = 16; o > 0; o >>= 1) {
            sum += __shfl_xor_sync(0xffffffffu, sum, o);
            ss  += __shfl_xor_sync(0xffffffffu, ss, o);
        }
        float mu = sum * (1.f / 128.f);
        float rstd = rsqrtf(fmaxf(ss * (1.f / 128.f) - mu * mu, 0.f) + 1e-5f);
        int gr = row0 + r;
        if (gr < M) {
            float o0 = fmaxf(fmaf((v.x - mu) * rstd, g4.x, b4.x), 0.f);
            float o1 = fmaxf(fmaf((v.y - mu) * rstd, g4.y, b4.y), 0.f);
            float o2 = fmaxf(fmaf((v.z - mu) * rstd, g4.z, b4.z), 0.f);
            float o3 = fmaxf(fmaf((v.w - mu) * rstd, g4.w, b4.w), 0.f);
            *reinterpret_cast<float4*>(out + (size_t)gr * C + cb) = make_float4(o0, o1, o2, o3);
            *reinterpret_cast<float4*>(aggz + (size_t)gr * C + cb) = z4;   // ready for next scatter
        }
    }
}

// ---------------- head ----------------
__global__ void head_kernel(const float* __restrict__ xu, const float* __restrict__ w,
                            const float* __restrict__ b, float* __restrict__ out) {
    int gid = blockIdx.x * blockDim.x + threadIdx.x;
    int wd = gid >> 5, lane = gid & 31;
    if (wd >= BB) return;
    float4 v  = *reinterpret_cast<const float4*>(xu + (size_t)wd * C + lane * 4);
    float4 ww = *reinterpret_cast<const float4*>(w + lane * 4);
    float s = v.x * ww.x + v.y * ww.y + v.z * ww.z + v.w * ww.w;
#pragma unroll
    for (int o = 16; o > 0; o >>= 1) s += __shfl_xor_sync(0xffffffffu, s, o);
    if (lane == 0) out[wd] = s + b[0];
}

// ---------------- launch: dead-code-eliminated dataflow ----------------
// Needed: scatter_ui0(full) -> gemmI0(full) -> scatter_iu1(dst<BB) -> gemmU1(4 CTAs) -> head
//         scatter_iu0(dst<BB) -> gemmU0(4 CTAs)   [provides xu_a rows 0..1023]
// Layer-1 item branch (scatter_ui1, gemmI1) is dead; gemmU rows >= 1024 are dead.
extern "C" void kernel_launch(void* const* d_in, const int* in_sizes, int n_in,
                              void* d_out, int out_size) {
    const float* x_user  = (const float*)d_in[0];
    const float* x_item  = (const float*)d_in[1];
    const int* e_ui_src  = (const int*)d_in[2];
    const int* e_ui_dst  = (const int*)d_in[3];
    const int* e_iu_src  = (const int*)d_in[4];
    const int* e_iu_dst  = (const int*)d_in[5];
    const float* w_rel   = (const float*)d_in[6];   // [L,2,C,C]
    const float* w_root  = (const float*)d_in[7];
    const float* bias    = (const float*)d_in[8];   // [L,2,C]
    const float* ln_g    = (const float*)d_in[9];
    const float* ln_b    = (const float*)d_in[10];
    const float* lin_w   = (const float*)d_in[11];
    const float* lin_b   = (const float*)d_in[12];
    float* out = (float*)d_out;

    float *xu_a, *xu_b, *xi_a, *aggu, *aggi;
    uint4* wfrag;
    cudaGetSymbolAddress((void**)&xu_a, g_xu_a);
    cudaGetSymbolAddress((void**)&xu_b, g_xu_b);
    cudaGetSymbolAddress((void**)&xi_a, g_xi_a);
    cudaGetSymbolAddress((void**)&aggu, g_agg_u);
    cudaGetSymbolAddress((void**)&aggi, g_agg_i);
    cudaGetSymbolAddress((void**)&wfrag, g_wfrag);

    cudaFuncSetAttribute(gemm_tc, cudaFuncAttributeMaxDynamicSharedMemorySize, GEMM_SMEM_BYTES);

    cudaStream_t sB = 0;
    cudaEvent_t evFork = 0, evU0 = 0;
    bool multi = (cudaStreamCreateWithFlags(&sB, cudaStreamNonBlocking) == cudaSuccess);
    if (multi) multi =
        (cudaEventCreateWithFlags(&evFork, cudaEventDisableTiming) == cudaSuccess) &&
        (cudaEventCreateWithFlags(&evU0,   cudaEventDisableTiming) == cudaSuccess);
    cudaStream_t sU = multi ? sB : (cudaStream_t)0;   // user-chain stream

    const int SBLK  = ((EE / 8) * 32 + 255) / 256;
    const int SBLKF = ((EE / 16) * 32 + 255) / 256;

    prep_w<<<(4 * 16 * 16 * 32 + 255) / 256, 256>>>(w_rel, w_root, wfrag);
    if (multi) {
        cudaEventRecord(evFork, 0);
        cudaStreamWaitEvent(sU, evFork, 0);
    }

    // ---- user chain (sU): filtered item->user scatter, 4-CTA gemmU0 ----
    scatter_filt_kernel<<<SBLKF, 256, 0, sU>>>(x_item, e_iu_src, e_iu_dst, aggu, EE);
    gemm_tc<<<NBLK_H, 512, GEMM_SMEM_BYTES, sU>>>(
        aggu, x_user, aggu, wfrag + (size_t)1 * 16 * 16 * 32,
        bias + 1 * C, ln_g + 0 * C, ln_b + 0 * C, xu_a, NU);
    if (multi) cudaEventRecord(evU0, sU);

    // ---- item chain (stream 0): full user->item scatter, full gemmI0 ----
    scatter_kernel<<<SBLK, 256, 0, 0>>>(x_user, e_ui_src, e_ui_dst, aggi, EE);
    gemm_tc<<<NBLK_I, 512, GEMM_SMEM_BYTES, 0>>>(
        aggi, x_item, aggi, wfrag + (size_t)0 * 16 * 16 * 32,
        bias + 0 * C, ln_g + 1 * C, ln_b + 1 * C, xi_a, NI);

    // ---- layer 1 (user side only) ----
    if (multi) cudaStreamWaitEvent(0, evU0, 0);   // aggu rows<BB re-zeroed; xu_a ready
    scatter_filt_kernel<<<SBLKF, 256, 0, 0>>>(xi_a, e_iu_src, e_iu_dst, aggu, EE);
    gemm_tc<<<NBLK_H, 512, GEMM_SMEM_BYTES, 0>>>(
        aggu, xu_a, aggu, wfrag + (size_t)3 * 16 * 16 * 32,
        bias + 3 * C, ln_g + 2 * C, ln_b + 2 * C, xu_b, NU);

    head_kernel<<<(BB * 32 + 255) / 256, 256, 0, 0>>>(xu_b, lin_w, lin_b, out);
}

// round 15
// speedup vs baseline: 5.2686x; 1.6929x over previous
#include <cuda_runtime.h>
#include <cuda_fp16.h>
#include <cstdint>

#define NU 100000
#define NI 50000
#define EE 500000
#define C  128
#define LL 2
#define BB 1024

#define NBLK_I ((NI + 255) / 256)   // 196 (max tiles for gathered gemm)
#define NBLK_H ((BB + 255) / 256)   // 4
#define BM_WORDS ((NI + 31) / 32)

// ---------------- static device scratch ----------------
__device__ float g_xu_a[NU * C];
__device__ float g_xu_b[NU * C];
__device__ float g_xi_a[NI * C];
__device__ float g_agg_u[NU * C];
__device__ float g_agg_i[NI * C];
__device__ __align__(16) uint4 g_wfrag[4 * 16 * 16 * 32];
// demand sets (rebuilt every replay inside the graph)
__device__ int g_ecount;
__device__ int g_icount;
__device__ int g_elist[EE];
__device__ int g_ilist[NI];
__device__ uint32_t g_bitmap[BM_WORDS];

// ---------------- helpers ----------------
__device__ __forceinline__ uint32_t h2u(half2 h) { return *reinterpret_cast<uint32_t*>(&h); }
__device__ __forceinline__ void split16(float x, half& h, half& l) {
    h = __float2half_rn(x);
    l = __float2half_rn(x - __half2float(h));
}
__device__ __forceinline__ void split2(float2 v, uint32_t& hi, uint32_t& lo) {
    half2 h = __float22half2_rn(v);
    float2 hf = __half22float2(h);
    half2 l = __float22half2_rn(make_float2(v.x - hf.x, v.y - hf.y));
    hi = h2u(h);
    lo = h2u(l);
}
__device__ __forceinline__ void mma16(float* c, uint32_t a0, uint32_t a1, uint32_t a2, uint32_t a3,
                                      uint32_t b0, uint32_t b1) {
    asm("mma.sync.aligned.m16n8k16.row.col.f32.f16.f16.f32 "
        "{%0,%1,%2,%3},{%4,%5,%6,%7},{%8,%9},{%0,%1,%2,%3};"
        : "+f"(c[0]), "+f"(c[1]), "+f"(c[2]), "+f"(c[3])
        : "r"(a0), "r"(a1), "r"(a2), "r"(a3), "r"(b0), "r"(b1));
}
__device__ __forceinline__ uint32_t smem_u32(const void* p) {
    uint32_t a;
    asm("{ .reg .u64 t; cvta.to.shared.u64 t, %1; cvt.u32.u64 %0, t; }" : "=r"(a) : "l"(p));
    return a;
}
#define CP_ASYNC16(dst_u32, src_ptr) \
    asm volatile("cp.async.cg.shared.global [%0], [%1], 16;" :: "r"(dst_u32), "l"(src_ptr) : "memory")
#define CP_COMMIT() asm volatile("cp.async.commit_group;" ::: "memory")
#define CP_WAIT(n)  asm volatile("cp.async.wait_group %0;" :: "n"(n) : "memory")
#define RED4(dptr, v) \
    asm volatile("red.global.add.v4.f32 [%0], {%1, %2, %3, %4};" \
                 :: "l"(dptr), "f"((v).x), "f"((v).y), "f"((v).z), "f"((v).w) : "memory")

// ---------------- reset demand-set state ----------------
__global__ void reset_kernel() {
    int i = blockIdx.x * blockDim.x + threadIdx.x;
    if (i == 0) { g_ecount = 0; g_icount = 0; }
    for (int j = i; j < BM_WORDS; j += gridDim.x * blockDim.x) g_bitmap[j] = 0;
}

// ---------------- compact: iu-edges with dst<BB -> elist; dedup srcs -> ilist + bitmap ----------------
__global__ void compact_kernel(const int* __restrict__ src, const int* __restrict__ dst) {
    int i4 = blockIdx.x * blockDim.x + threadIdx.x;
    if (i4 * 4 >= EE) return;
    int4 d4 = *reinterpret_cast<const int4*>(dst + i4 * 4);
    int dd[4] = {d4.x, d4.y, d4.z, d4.w};
#pragma unroll
    for (int j = 0; j < 4; ++j) {
        if (dd[j] < BB) {
            int e = i4 * 4 + j;
            int s = __ldg(src + e);
            int eidx = atomicAdd(&g_ecount, 1);
            g_elist[eidx] = e;
            uint32_t bit = 1u << (s & 31);
            uint32_t old = atomicOr(&g_bitmap[s >> 5], bit);
            if (!(old & bit)) {
                int ii = atomicAdd(&g_icount, 1);
                g_ilist[ii] = s;
            }
        }
    }
}

// ---------------- bitmap-filtered scatter: ui-edges whose dst item is needed ----------------
__global__ void scatter_bm_kernel(const float* __restrict__ x, const int* __restrict__ src,
                                  const int* __restrict__ dst, float* __restrict__ agg, int E) {
    int gid = blockIdx.x * blockDim.x + threadIdx.x;
    int w = gid >> 5;
    int lane = gid & 31;
    int e0 = w * 16;
    if (e0 >= E) return;
    int d[16];
    *reinterpret_cast<int4*>(d)      = *reinterpret_cast<const int4*>(dst + e0);
    *reinterpret_cast<int4*>(d + 4)  = *reinterpret_cast<const int4*>(dst + e0 + 4);
    *reinterpret_cast<int4*>(d + 8)  = *reinterpret_cast<const int4*>(dst + e0 + 8);
    *reinterpret_cast<int4*>(d + 12) = *reinterpret_cast<const int4*>(dst + e0 + 12);
#pragma unroll
    for (int j = 0; j < 16; ++j) {
        if ((g_bitmap[d[j] >> 5] >> (d[j] & 31)) & 1u) {
            int s = __ldg(src + e0 + j);
            float4 v = __ldg(reinterpret_cast<const float4*>(x + (size_t)s * C) + lane);
            RED4(agg + (size_t)d[j] * C + lane * 4, v);
        }
    }
}

// ---------------- edge-list scatter: warp per compacted edge ----------------
__global__ void scatter_list_kernel(const float* __restrict__ x, const int* __restrict__ src,
                                    const int* __restrict__ dst, float* __restrict__ agg) {
    int nw = (gridDim.x * blockDim.x) >> 5;
    int w = (blockIdx.x * blockDim.x + threadIdx.x) >> 5;
    int lane = threadIdx.x & 31;
    int cnt = g_ecount;
    for (; w < cnt; w += nw) {
        int e = g_elist[w];
        int s = __ldg(src + e);
        int dd = __ldg(dst + e);
        float4 v = __ldg(reinterpret_cast<const float4*>(x + (size_t)s * C) + lane);
        RED4(agg + (size_t)dd * C + lane * 4, v);
    }
}

// ---------------- weight prep ----------------
__global__ void prep_w(const float* __restrict__ wrel, const float* __restrict__ wroot,
                       uint4* __restrict__ outw) {
    int gid = blockIdx.x * blockDim.x + threadIdx.x;   // [lt][k16][nt][lane]
    if (gid >= 4 * 16 * 16 * 32) return;
    int lane = gid & 31;
    int nt   = (gid >> 5) & 15;
    int k16  = (gid >> 9) & 15;
    int lt   = gid >> 13;
    int n  = nt * 8 + (lane >> 2);
    int k0 = k16 * 16 + (lane & 3) * 2;
    float w[4];
#pragma unroll
    for (int j = 0; j < 4; ++j) {
        int k = k0 + (j >> 1) * 8 + (j & 1);
        w[j] = (k < 128) ? wrel[((size_t)lt * 128 + k) * 128 + n]
                         : wroot[((size_t)lt * 128 + (k - 128)) * 128 + n];
    }
    half h[4], l[4];
#pragma unroll
    for (int j = 0; j < 4; ++j) split16(w[j], h[j], l[j]);
    outw[gid] = make_uint4(h2u(__halves2half2(h[0], h[1])), h2u(__halves2half2(h[2], h[3])),
                           h2u(__halves2half2(l[0], l[1])), h2u(__halves2half2(l[2], l[3])));
}

// ---------------- shared GEMM core (round-11) via macro body with row mapping ----------------
#define W_SMEM_U4 (16 * 16 * 32)
#define AS_STRIDE 20
#define ABUF_F (256 * AS_STRIDE)
#define SM_ABASE 32768
#define O_STRIDE 132
#define GEMM_SMEM_BYTES ((SM_ABASE + 3 * ABUF_F) * 4)

// direct version: rows row0..row0+255 (clamped), guard gr < M
__global__ void __launch_bounds__(512, 1) gemm_tc(
    const float* __restrict__ agg, const float* __restrict__ xin,
    float* aggz, const uint4* __restrict__ wfrag,
    const float* __restrict__ bias, const float* __restrict__ gln, const float* __restrict__ blnv,
    float* __restrict__ out, int M)
{
    extern __shared__ float smem[];
    uint4* sw = reinterpret_cast<uint4*>(smem);
    const int tid  = threadIdx.x;
    const int lane = tid & 31;
    const int wid  = tid >> 5;
    const int wm   = wid >> 1;
    const int wn   = wid & 1;
    const int row0 = blockIdx.x * 256;

    const int crow  = tid >> 1;
    const int chalf = tid & 1;
    int gcr = row0 + crow; if (gcr > M - 1) gcr = M - 1;
    const size_t csrc_off = (size_t)gcr * C + chalf * 8;
    uint32_t cdst[3];
#pragma unroll
    for (int b = 0; b < 3; ++b)
        cdst[b] = smem_u32(smem + SM_ABASE + b * ABUF_F + crow * AS_STRIDE + chalf * 8);

#define ISSUE(st) do {                                                              \
        const float* sp = (((st) < 8) ? agg : xin) + csrc_off + ((st) & 7) * 16;    \
        uint32_t d = cdst[(st) % 3];                                                \
        CP_ASYNC16(d, sp);                                                          \
        CP_ASYNC16(d + 16, sp + 4);                                                 \
        CP_COMMIT();                                                                \
    } while (0)

    ISSUE(0);
    ISSUE(1);
#pragma unroll
    for (int i = 0; i < W_SMEM_U4 / 512; ++i)
        sw[i * 512 + tid] = __ldg(wfrag + i * 512 + tid);

    const int kq = 2 * (lane & 3);
    float c[2][8][4];
#pragma unroll
    for (int nt = 0; nt < 8; ++nt) {
        int col = wn * 64 + nt * 8 + kq;
        float b0 = __ldg(bias + col), b1 = __ldg(bias + col + 1);
#pragma unroll
        for (int mt = 0; mt < 2; ++mt) {
            c[mt][nt][0] = b0; c[mt][nt][1] = b1;
            c[mt][nt][2] = b0; c[mt][nt][3] = b1;
        }
    }
    __syncthreads();

#pragma unroll
    for (int s = 0; s < 16; ++s) {
        if (s == 15) CP_WAIT(0); else CP_WAIT(1);
        __syncthreads();
        if (s + 2 < 16) ISSUE(s + 2);
        const float* ab = smem + SM_ABASE + (s % 3) * ABUF_F;
        uint32_t ah[2][4], al[2][4];
#pragma unroll
        for (int mt = 0; mt < 2; ++mt) {
            const int rb = wm * 32 + mt * 16 + (lane >> 2);
            float2 f0 = *reinterpret_cast<const float2*>(ab + rb * AS_STRIDE + kq);
            float2 f1 = *reinterpret_cast<const float2*>(ab + (rb + 8) * AS_STRIDE + kq);
            float2 f2 = *reinterpret_cast<const float2*>(ab + rb * AS_STRIDE + kq + 8);
            float2 f3 = *reinterpret_cast<const float2*>(ab + (rb + 8) * AS_STRIDE + kq + 8);
            split2(f0, ah[mt][0], al[mt][0]);
            split2(f1, ah[mt][1], al[mt][1]);
            split2(f2, ah[mt][2], al[mt][2]);
            split2(f3, ah[mt][3], al[mt][3]);
        }
        const uint4* wp = sw + ((size_t)s * 16 + wn * 8) * 32 + lane;
#pragma unroll
        for (int nt = 0; nt < 8; ++nt) {
            uint4 bf = wp[nt * 32];
#pragma unroll
            for (int mt = 0; mt < 2; ++mt) {
                mma16(c[mt][nt], ah[mt][0], ah[mt][1], ah[mt][2], ah[mt][3], bf.x, bf.y);
                mma16(c[mt][nt], al[mt][0], al[mt][1], al[mt][2], al[mt][3], bf.x, bf.y);
                mma16(c[mt][nt], ah[mt][0], ah[mt][1], ah[mt][2], ah[mt][3], bf.z, bf.w);
            }
        }
    }
#undef ISSUE
    __syncthreads();

#pragma unroll
    for (int mt = 0; mt < 2; ++mt) {
        int r = wm * 32 + mt * 16 + (lane >> 2);
#pragma unroll
        for (int nt = 0; nt < 8; ++nt) {
            int col = wn * 64 + nt * 8 + kq;
            *reinterpret_cast<float2*>(smem + (size_t)r * O_STRIDE + col)       = make_float2(c[mt][nt][0], c[mt][nt][1]);
            *reinterpret_cast<float2*>(smem + (size_t)(r + 8) * O_STRIDE + col) = make_float2(c[mt][nt][2], c[mt][nt][3]);
        }
    }
    __syncthreads();

    const int cb = lane * 4;
    const float4 z4 = make_float4(0.f, 0.f, 0.f, 0.f);
    float4 g4 = __ldg(reinterpret_cast<const float4*>(gln + cb));
    float4 b4 = __ldg(reinterpret_cast<const float4*>(blnv + cb));
#pragma unroll 4
    for (int it = 0; it < 16; ++it) {
        int r = wid * 16 + it;
        float4 v = *reinterpret_cast<const float4*>(smem + (size_t)r * O_STRIDE + cb);
        float sum = v.x + v.y + v.z + v.w;
        float ss  = v.x * v.x + v.y * v.y + v.z * v.z + v.w * v.w;
#pragma unroll
        for (int o = 16; o > 0; o >>= 1) {
            sum += __shfl_xor_sync(0xffffffffu, sum, o);
            ss  += __shfl_xor_sync(0xffffffffu, ss, o);
        }
        float mu = sum * (1.f / 128.f);
        float rstd = rsqrtf(fmaxf(ss * (1.f / 128.f) - mu * mu, 0.f) + 1e-5f);
        int gr = row0 + r;
        if (gr < M) {
            float o0 = fmaxf(fmaf((v.x - mu) * rstd, g4.x, b4.x), 0.f);
            float o1 = fmaxf(fmaf((v.y - mu) * rstd, g4.y, b4.y), 0.f);
            float o2 = fmaxf(fmaf((v.z - mu) * rstd, g4.z, b4.z), 0.f);
            float o3 = fmaxf(fmaf((v.w - mu) * rstd, g4.w, b4.w), 0.f);
            *reinterpret_cast<float4*>(out + (size_t)gr * C + cb) = make_float4(o0, o1, o2, o3);
            *reinterpret_cast<float4*>(aggz + (size_t)gr * C + cb) = z4;
        }
    }
}

// gathered version: logical rows come from g_ilist[0..g_icount); scat-writes out + re-zeroes agg
__global__ void __launch_bounds__(512, 1) gemm_tc_gather(
    const float* __restrict__ agg, const float* __restrict__ xin,
    float* aggz, const uint4* __restrict__ wfrag,
    const float* __restrict__ bias, const float* __restrict__ gln, const float* __restrict__ blnv,
    float* __restrict__ out)
{
    extern __shared__ float smem[];
    uint4* sw = reinterpret_cast<uint4*>(smem);
    const int cnt = g_icount;
    const int base = blockIdx.x * 256;
    if (base >= cnt) return;

    const int tid  = threadIdx.x;
    const int lane = tid & 31;
    const int wid  = tid >> 5;
    const int wm   = wid >> 1;
    const int wn   = wid & 1;

    const int crow  = tid >> 1;
    const int chalf = tid & 1;
    int ridx = base + crow; if (ridx > cnt - 1) ridx = cnt - 1;
    const int gcr = g_ilist[ridx];
    const size_t csrc_off = (size_t)gcr * C + chalf * 8;
    uint32_t cdst[3];
#pragma unroll
    for (int b = 0; b < 3; ++b)
        cdst[b] = smem_u32(smem + SM_ABASE + b * ABUF_F + crow * AS_STRIDE + chalf * 8);

#define ISSUE(st) do {                                                              \
        const float* sp = (((st) < 8) ? agg : xin) + csrc_off + ((st) & 7) * 16;    \
        uint32_t d = cdst[(st) % 3];                                                \
        CP_ASYNC16(d, sp);                                                          \
        CP_ASYNC16(d + 16, sp + 4);                                                 \
        CP_COMMIT();                                                                \
    } while (0)

    ISSUE(0);
    ISSUE(1);
#pragma unroll
    for (int i = 0; i < W_SMEM_U4 / 512; ++i)
        sw[i * 512 + tid] = __ldg(wfrag + i * 512 + tid);

    const int kq = 2 * (lane & 3);
    float c[2][8][4];
#pragma unroll
    for (int nt = 0; nt < 8; ++nt) {
        int col = wn * 64 + nt * 8 + kq;
        float b0 = __ldg(bias + col), b1 = __ldg(bias + col + 1);
#pragma unroll
        for (int mt = 0; mt < 2; ++mt) {
            c[mt][nt][0] = b0; c[mt][nt][1] = b1;
            c[mt][nt][2] = b0; c[mt][nt][3] = b1;
        }
    }
    __syncthreads();

#pragma unroll
    for (int s = 0; s < 16; ++s) {
        if (s == 15) CP_WAIT(0); else CP_WAIT(1);
        __syncthreads();
        if (s + 2 < 16) ISSUE(s + 2);
        const float* ab = smem + SM_ABASE + (s % 3) * ABUF_F;
        uint32_t ah[2][4], al[2][4];
#pragma unroll
        for (int mt = 0; mt < 2; ++mt) {
            const int rb = wm * 32 + mt * 16 + (lane >> 2);
            float2 f0 = *reinterpret_cast<const float2*>(ab + rb * AS_STRIDE + kq);
            float2 f1 = *reinterpret_cast<const float2*>(ab + (rb + 8) * AS_STRIDE + kq);
            float2 f2 = *reinterpret_cast<const float2*>(ab + rb * AS_STRIDE + kq + 8);
            float2 f3 = *reinterpret_cast<const float2*>(ab + (rb + 8) * AS_STRIDE + kq + 8);
            split2(f0, ah[mt][0], al[mt][0]);
            split2(f1, ah[mt][1], al[mt][1]);
            split2(f2, ah[mt][2], al[mt][2]);
            split2(f3, ah[mt][3], al[mt][3]);
        }
        const uint4* wp = sw + ((size_t)s * 16 + wn * 8) * 32 + lane;
#pragma unroll
        for (int nt = 0; nt < 8; ++nt) {
            uint4 bf = wp[nt * 32];
#pragma unroll
            for (int mt = 0; mt < 2; ++mt) {
                mma16(c[mt][nt], ah[mt][0], ah[mt][1], ah[mt][2], ah[mt][3], bf.x, bf.y);
                mma16(c[mt][nt], al[mt][0], al[mt][1], al[mt][2], al[mt][3], bf.x, bf.y);
                mma16(c[mt][nt], ah[mt][0], ah[mt][1], ah[mt][2], ah[mt][3], bf.z, bf.w);
            }
        }
    }
#undef ISSUE
    __syncthreads();

#pragma unroll
    for (int mt = 0; mt < 2; ++mt) {
        int r = wm * 32 + mt * 16 + (lane >> 2);
#pragma unroll
        for (int nt = 0; nt < 8; ++nt) {
            int col = wn * 64 + nt * 8 + kq;
            *reinterpret_cast<float2*>(smem + (size_t)r * O_STRIDE + col)       = make_float2(c[mt][nt][0], c[mt][nt][1]);
            *reinterpret_cast<float2*>(smem + (size_t)(r + 8) * O_STRIDE + col) = make_float2(c[mt][nt][2], c[mt][nt][3]);
        }
    }
    __syncthreads();

    const int cb = lane * 4;
    const float4 z4 = make_float4(0.f, 0.f, 0.f, 0.f);
    float4 g4 = __ldg(reinterpret_cast<const float4*>(gln + cb));
    float4 b4 = __ldg(reinterpret_cast<const float4*>(blnv + cb));
#pragma unroll 4
    for (int it = 0; it < 16; ++it) {
        int r = wid * 16 + it;
        float4 v = *reinterpret_cast<const float4*>(smem + (size_t)r * O_STRIDE + cb);
        float sum = v.x + v.y + v.z + v.w;
        float ss  = v.x * v.x + v.y * v.y + v.z * v.z + v.w * v.w;
#pragma unroll
        for (int o = 16; o > 0; o >>= 1) {
            sum += __shfl_xor_sync(0xffffffffu, sum, o);
            ss  += __shfl_xor_sync(0xffffffffu, ss, o);
        }
        float mu = sum * (1.f / 128.f);
        float rstd = rsqrtf(fmaxf(ss * (1.f / 128.f) - mu * mu, 0.f) + 1e-5f);
        if (base + r < cnt) {
            int gr = g_ilist[base + r];
            float o0 = fmaxf(fmaf((v.x - mu) * rstd, g4.x, b4.x), 0.f);
            float o1 = fmaxf(fmaf((v.y - mu) * rstd, g4.y, b4.y), 0.f);
            float o2 = fmaxf(fmaf((v.z - mu) * rstd, g4.z, b4.z), 0.f);
            float o3 = fmaxf(fmaf((v.w - mu) * rstd, g4.w, b4.w), 0.f);
            *reinterpret_cast<float4*>(out + (size_t)gr * C + cb) = make_float4(o0, o1, o2, o3);
            *reinterpret_cast<float4*>(aggz + (size_t)gr * C + cb) = z4;
        }
    }
}

// ---------------- head ----------------
__global__ void head_kernel(const float* __restrict__ xu, const float* __restrict__ w,
                            const float* __restrict__ b, float* __restrict__ out) {
    int gid = blockIdx.x * blockDim.x + threadIdx.x;
    int wd = gid >> 5, lane = gid & 31;
    if (wd >= BB) return;
    float4 v  = *reinterpret_cast<const float4*>(xu + (size_t)wd * C + lane * 4);
    float4 ww = *reinterpret_cast<const float4*>(w + lane * 4);
    float s = v.x * ww.x + v.y * ww.y + v.z * ww.z + v.w * ww.w;
#pragma unroll
    for (int o = 16; o > 0; o >>= 1) s += __shfl_xor_sync(0xffffffffu, s, o);
    if (lane == 0) out[wd] = s + b[0];
}

// ---------------- launch: demand-driven dataflow ----------------
extern "C" void kernel_launch(void* const* d_in, const int* in_sizes, int n_in,
                              void* d_out, int out_size) {
    const float* x_user  = (const float*)d_in[0];
    const float* x_item  = (const float*)d_in[1];
    const int* e_ui_src  = (const int*)d_in[2];
    const int* e_ui_dst  = (const int*)d_in[3];
    const int* e_iu_src  = (const int*)d_in[4];
    const int* e_iu_dst  = (const int*)d_in[5];
    const float* w_rel   = (const float*)d_in[6];
    const float* w_root  = (const float*)d_in[7];
    const float* bias    = (const float*)d_in[8];
    const float* ln_g    = (const float*)d_in[9];
    const float* ln_b    = (const float*)d_in[10];
    const float* lin_w   = (const float*)d_in[11];
    const float* lin_b   = (const float*)d_in[12];
    float* out = (float*)d_out;

    float *xu_a, *xu_b, *xi_a, *aggu, *aggi;
    uint4* wfrag;
    cudaGetSymbolAddress((void**)&xu_a, g_xu_a);
    cudaGetSymbolAddress((void**)&xu_b, g_xu_b);
    cudaGetSymbolAddress((void**)&xi_a, g_xi_a);
    cudaGetSymbolAddress((void**)&aggu, g_agg_u);
    cudaGetSymbolAddress((void**)&aggi, g_agg_i);
    cudaGetSymbolAddress((void**)&wfrag, g_wfrag);

    cudaFuncSetAttribute(gemm_tc, cudaFuncAttributeMaxDynamicSharedMemorySize, GEMM_SMEM_BYTES);
    cudaFuncSetAttribute(gemm_tc_gather, cudaFuncAttributeMaxDynamicSharedMemorySize, GEMM_SMEM_BYTES);

    cudaStream_t sB = 0;
    cudaEvent_t evC = 0, evU0 = 0;
    bool multi = (cudaStreamCreateWithFlags(&sB, cudaStreamNonBlocking) == cudaSuccess);
    if (multi) multi =
        (cudaEventCreateWithFlags(&evC,  cudaEventDisableTiming) == cudaSuccess) &&
        (cudaEventCreateWithFlags(&evU0, cudaEventDisableTiming) == cudaSuccess);
    cudaStream_t sU = multi ? sB : (cudaStream_t)0;

    const int SBLKB = ((EE / 16) * 32 + 255) / 256;   // bitmap scatter (16 edges/warp)

    // stream0: prep + demand-set construction
    prep_w<<<(4 * 16 * 16 * 32 + 255) / 256, 256>>>(w_rel, w_root, wfrag);
    reset_kernel<<<8, 256>>>();
    compact_kernel<<<(EE / 4 + 255) / 256, 256>>>(e_iu_src, e_iu_dst);
    if (multi) cudaEventRecord(evC, 0);

    // user chain L0 (sU): elist scatter x_item -> aggu[<BB], then 4-CTA gemmU0 -> xu_a
    if (multi) cudaStreamWaitEvent(sU, evC, 0);
    scatter_list_kernel<<<128, 256, 0, sU>>>(x_item, e_iu_src, e_iu_dst, aggu);
    gemm_tc<<<NBLK_H, 512, GEMM_SMEM_BYTES, sU>>>(
        aggu, x_user, aggu, wfrag + (size_t)1 * 16 * 16 * 32,
        bias + 1 * C, ln_g + 0 * C, ln_b + 0 * C, xu_a, NU);
    if (multi) cudaEventRecord(evU0, sU);

    // item chain L0 (stream0): bitmap-filtered ui scatter -> gathered gemmI0 -> xi_a (needed rows)
    scatter_bm_kernel<<<SBLKB, 256, 0, 0>>>(x_user, e_ui_src, e_ui_dst, aggi, EE);
    gemm_tc_gather<<<NBLK_I, 512, GEMM_SMEM_BYTES, 0>>>(
        aggi, x_item, aggi, wfrag + (size_t)0 * 16 * 16 * 32,
        bias + 0 * C, ln_g + 1 * C, ln_b + 1 * C, xi_a);

    // layer 1 user side: elist scatter xi_a -> aggu[<BB] (after gemmU0 re-zeroed aggu), gemmU1
    if (multi) cudaStreamWaitEvent(0, evU0, 0);
    scatter_list_kernel<<<128, 256, 0, 0>>>(xi_a, e_iu_src, e_iu_dst, aggu);
    gemm_tc<<<NBLK_H, 512, GEMM_SMEM_BYTES, 0>>>(
        aggu, xu_a, aggu, wfrag + (size_t)3 * 16 * 16 * 32,
        bias + 3 * C, ln_g + 2 * C, ln_b + 2 * C, xu_b, NU);

    head_kernel<<<(BB * 32 + 255) / 256, 256, 0, 0>>>(xu_b, lin_w, lin_b, out);
}

// round 16
// speedup vs baseline: 8.0403x; 1.5261x over previous
#include <cuda_runtime.h>
#include <cuda_fp16.h>
#include <cstdint>

#define NU 100000
#define NI 50000
#define EE 500000
#define C  128
#define LL 2
#define BB 1024

#define MT 64                         // gemm rows per CTA
#define NBLK_H (BB / MT)              // 16
#define NBLK_IG ((NI + MT - 1) / MT)  // 782 (max tiles for gathered gemm; most early-exit)
#define BM_WORDS ((NI + 31) / 32)

// ---------------- static device scratch ----------------
__device__ float g_xu_a[NU * C];
__device__ float g_xu_b[NU * C];
__device__ float g_xi_a[NI * C];
__device__ float g_agg_u[NU * C];
__device__ float g_agg_i[NI * C];
__device__ __align__(16) uint4 g_wfrag[4 * 16 * 16 * 32];
// demand sets (rebuilt every replay inside the graph)
__device__ int g_ecount;
__device__ int g_icount;
__device__ int g_elist[EE];
__device__ int g_ilist[NI];
__device__ uint32_t g_bitmap[BM_WORDS];

// ---------------- helpers ----------------
__device__ __forceinline__ uint32_t h2u(half2 h) { return *reinterpret_cast<uint32_t*>(&h); }
__device__ __forceinline__ void split16(float x, half& h, half& l) {
    h = __float2half_rn(x);
    l = __float2half_rn(x - __half2float(h));
}
__device__ __forceinline__ void split2(float2 v, uint32_t& hi, uint32_t& lo) {
    half2 h = __float22half2_rn(v);
    float2 hf = __half22float2(h);
    half2 l = __float22half2_rn(make_float2(v.x - hf.x, v.y - hf.y));
    hi = h2u(h);
    lo = h2u(l);
}
__device__ __forceinline__ void mma16(float* c, uint32_t a0, uint32_t a1, uint32_t a2, uint32_t a3,
                                      uint32_t b0, uint32_t b1) {
    asm("mma.sync.aligned.m16n8k16.row.col.f32.f16.f16.f32 "
        "{%0,%1,%2,%3},{%4,%5,%6,%7},{%8,%9},{%0,%1,%2,%3};"
        : "+f"(c[0]), "+f"(c[1]), "+f"(c[2]), "+f"(c[3])
        : "r"(a0), "r"(a1), "r"(a2), "r"(a3), "r"(b0), "r"(b1));
}
__device__ __forceinline__ uint32_t smem_u32(const void* p) {
    uint32_t a;
    asm("{ .reg .u64 t; cvta.to.shared.u64 t, %1; cvt.u32.u64 %0, t; }" : "=r"(a) : "l"(p));
    return a;
}
#define CP_ASYNC16(dst_u32, src_ptr) \
    asm volatile("cp.async.cg.shared.global [%0], [%1], 16;" :: "r"(dst_u32), "l"(src_ptr) : "memory")
#define CP_COMMIT() asm volatile("cp.async.commit_group;" ::: "memory")
#define CP_WAIT(n)  asm volatile("cp.async.wait_group %0;" :: "n"(n) : "memory")
#define RED4(dptr, v) \
    asm volatile("red.global.add.v4.f32 [%0], {%1, %2, %3, %4};" \
                 :: "l"(dptr), "f"((v).x), "f"((v).y), "f"((v).z), "f"((v).w) : "memory")

// ---------------- reset demand-set state ----------------
__global__ void reset_kernel() {
    int i = blockIdx.x * blockDim.x + threadIdx.x;
    if (i == 0) { g_ecount = 0; g_icount = 0; }
    for (int j = i; j < BM_WORDS; j += gridDim.x * blockDim.x) g_bitmap[j] = 0;
}

// ---------------- compact: iu-edges with dst<BB -> elist; dedup srcs -> ilist + bitmap ----------------
__global__ void compact_kernel(const int* __restrict__ src, const int* __restrict__ dst) {
    int i4 = blockIdx.x * blockDim.x + threadIdx.x;
    if (i4 * 4 >= EE) return;
    int4 d4 = *reinterpret_cast<const int4*>(dst + i4 * 4);
    int dd[4] = {d4.x, d4.y, d4.z, d4.w};
#pragma unroll
    for (int j = 0; j < 4; ++j) {
        if (dd[j] < BB) {
            int e = i4 * 4 + j;
            int s = __ldg(src + e);
            int eidx = atomicAdd(&g_ecount, 1);
            g_elist[eidx] = e;
            uint32_t bit = 1u << (s & 31);
            uint32_t old = atomicOr(&g_bitmap[s >> 5], bit);
            if (!(old & bit)) {
                int ii = atomicAdd(&g_icount, 1);
                g_ilist[ii] = s;
            }
        }
    }
}

// ---------------- bitmap-filtered scatter: ui-edges whose dst item is needed ----------------
__global__ void scatter_bm_kernel(const float* __restrict__ x, const int* __restrict__ src,
                                  const int* __restrict__ dst, float* __restrict__ agg, int E) {
    int gid = blockIdx.x * blockDim.x + threadIdx.x;
    int w = gid >> 5;
    int lane = gid & 31;
    int e0 = w * 16;
    if (e0 >= E) return;
    int d[16];
    *reinterpret_cast<int4*>(d)      = *reinterpret_cast<const int4*>(dst + e0);
    *reinterpret_cast<int4*>(d + 4)  = *reinterpret_cast<const int4*>(dst + e0 + 4);
    *reinterpret_cast<int4*>(d + 8)  = *reinterpret_cast<const int4*>(dst + e0 + 8);
    *reinterpret_cast<int4*>(d + 12) = *reinterpret_cast<const int4*>(dst + e0 + 12);
#pragma unroll
    for (int j = 0; j < 16; ++j) {
        if ((g_bitmap[d[j] >> 5] >> (d[j] & 31)) & 1u) {
            int s = __ldg(src + e0 + j);
            float4 v = __ldg(reinterpret_cast<const float4*>(x + (size_t)s * C) + lane);
            RED4(agg + (size_t)d[j] * C + lane * 4, v);
        }
    }
}

// ---------------- edge-list scatter: 4 edges per warp in flight (MLP=4) ----------------
__global__ void scatter_list_kernel(const float* __restrict__ x, const int* __restrict__ src,
                                    const int* __restrict__ dst, float* __restrict__ agg) {
    int nw = (gridDim.x * blockDim.x) >> 5;
    int w = (blockIdx.x * blockDim.x + threadIdx.x) >> 5;
    int lane = threadIdx.x & 31;
    int cnt = g_ecount;
    for (int e4 = w * 4; e4 < cnt; e4 += nw * 4) {
        int n = cnt - e4; if (n > 4) n = 4;
        int e[4], s[4], d[4];
#pragma unroll
        for (int j = 0; j < 4; ++j) if (j < n) e[j] = g_elist[e4 + j];
#pragma unroll
        for (int j = 0; j < 4; ++j) if (j < n) { s[j] = __ldg(src + e[j]); d[j] = __ldg(dst + e[j]); }
        float4 v[4];
#pragma unroll
        for (int j = 0; j < 4; ++j) if (j < n)
            v[j] = __ldg(reinterpret_cast<const float4*>(x + (size_t)s[j] * C) + lane);
#pragma unroll
        for (int j = 0; j < 4; ++j) if (j < n)
            RED4(agg + (size_t)d[j] * C + lane * 4, v[j]);
    }
}

// ---------------- weight prep ----------------
__global__ void prep_w(const float* __restrict__ wrel, const float* __restrict__ wroot,
                       uint4* __restrict__ outw) {
    int gid = blockIdx.x * blockDim.x + threadIdx.x;   // [lt][k16][nt][lane]
    if (gid >= 4 * 16 * 16 * 32) return;
    int lane = gid & 31;
    int nt   = (gid >> 5) & 15;
    int k16  = (gid >> 9) & 15;
    int lt   = gid >> 13;
    int n  = nt * 8 + (lane >> 2);
    int k0 = k16 * 16 + (lane & 3) * 2;
    float w[4];
#pragma unroll
    for (int j = 0; j < 4; ++j) {
        int k = k0 + (j >> 1) * 8 + (j & 1);
        w[j] = (k < 128) ? wrel[((size_t)lt * 128 + k) * 128 + n]
                         : wroot[((size_t)lt * 128 + (k - 128)) * 128 + n];
    }
    half h[4], l[4];
#pragma unroll
    for (int j = 0; j < 4; ++j) split16(w[j], h[j], l[j]);
    outw[gid] = make_uint4(h2u(__halves2half2(h[0], h[1])), h2u(__halves2half2(h[2], h[3])),
                           h2u(__halves2half2(l[0], l[1])), h2u(__halves2half2(l[2], l[3])));
}

// ---------------- small-tile GEMM core: 64 rows/CTA, 512 thr, warp tile 16x32 ----------------
// Per-CTA latency ~4x lower than the 256-row tile (critical-path optimized).
// GEMM_BODY(ROW_STAGE_EXPR, ROW_OUT_EXPR, GUARD_EXPR) with crow/r in scope.
#define W_SMEM_U4 (16 * 16 * 32)
#define AS_STRIDE 20
#define ABUF_F (MT * AS_STRIDE)                    // 1280 floats
#define SM_ABASE 32768
#define O_STRIDE 132
#define GEMM_SMEM_BYTES ((SM_ABASE + 3 * ABUF_F) * 4)   // 146432

#define GEMM_CORE(GCR_STAGE, GR_OUT, GUARD)                                         \
    extern __shared__ float smem[];                                                 \
    uint4* sw = reinterpret_cast<uint4*>(smem);                                     \
    const int tid  = threadIdx.x;                                                   \
    const int lane = tid & 31;                                                      \
    const int wid  = tid >> 5;        /* 0..15 */                                   \
    const int wm   = wid >> 2;        /* 0..3: 16-row group */                      \
    const int wn   = wid & 3;         /* 0..3: 32-col group */                      \
    const int crow = tid >> 2;        /* staging row 0..127 -> use <64 */           \
    const int cq   = tid & 3;                                                       \
    const int gcr  = (GCR_STAGE);     /* global row for staging (tid<256) */        \
    const size_t csrc_off = (size_t)gcr * C + cq * 4;                               \
    uint32_t cdst[3];                                                               \
    _Pragma("unroll")                                                               \
    for (int b = 0; b < 3; ++b)                                                     \
        cdst[b] = smem_u32(smem + SM_ABASE + b * ABUF_F + (crow & 63) * AS_STRIDE + cq * 4); \
    /* stage 0,1 */                                                                 \
    if (tid < 256) {                                                                \
        CP_ASYNC16(cdst[0], agg + csrc_off);                                        \
        CP_COMMIT();                                                                \
        CP_ASYNC16(cdst[1], agg + csrc_off + 16);                                   \
        CP_COMMIT();                                                                \
    }                                                                               \
    _Pragma("unroll")                                                               \
    for (int i = 0; i < W_SMEM_U4 / 512; ++i)                                       \
        sw[i * 512 + tid] = __ldg(wfrag + i * 512 + tid);                           \
    const int kq = 2 * (lane & 3);                                                  \
    float c[4][4];                                                                  \
    _Pragma("unroll")                                                               \
    for (int nt = 0; nt < 4; ++nt) {                                                \
        int col = wn * 32 + nt * 8 + kq;                                            \
        float b0 = __ldg(bias + col), b1 = __ldg(bias + col + 1);                   \
        c[nt][0] = b0; c[nt][1] = b1; c[nt][2] = b0; c[nt][3] = b1;                 \
    }                                                                               \
    __syncthreads();                                                                \
    _Pragma("unroll")                                                               \
    for (int s = 0; s < 16; ++s) {                                                  \
        if (s == 15) CP_WAIT(0); else CP_WAIT(1);                                   \
        __syncthreads();                                                            \
        if (s + 2 < 16 && tid < 256) {                                              \
            const float* sp = ((s + 2 < 8) ? agg : xin) + csrc_off + ((s + 2) & 7) * 16; \
            CP_ASYNC16(cdst[(s + 2) % 3], sp);                                      \
            CP_COMMIT();                                                            \
        }                                                                           \
        const float* ab = smem + SM_ABASE + (s % 3) * ABUF_F;                       \
        const int rb = wm * 16 + (lane >> 2);                                       \
        float2 f0 = *reinterpret_cast<const float2*>(ab + rb * AS_STRIDE + kq);     \
        float2 f1 = *reinterpret_cast<const float2*>(ab + (rb + 8) * AS_STRIDE + kq); \
        float2 f2 = *reinterpret_cast<const float2*>(ab + rb * AS_STRIDE + kq + 8); \
        float2 f3 = *reinterpret_cast<const float2*>(ab + (rb + 8) * AS_STRIDE + kq + 8); \
        uint32_t ah[4], al[4];                                                      \
        split2(f0, ah[0], al[0]);                                                   \
        split2(f1, ah[1], al[1]);                                                   \
        split2(f2, ah[2], al[2]);                                                   \
        split2(f3, ah[3], al[3]);                                                   \
        const uint4* wp = sw + ((size_t)s * 16 + wn * 4) * 32 + lane;               \
        _Pragma("unroll")                                                           \
        for (int nt = 0; nt < 4; ++nt) {                                            \
            uint4 bf = wp[nt * 32];                                                 \
            mma16(c[nt], ah[0], ah[1], ah[2], ah[3], bf.x, bf.y);                   \
            mma16(c[nt], al[0], al[1], al[2], al[3], bf.x, bf.y);                   \
            mma16(c[nt], ah[0], ah[1], ah[2], ah[3], bf.z, bf.w);                   \
        }                                                                           \
    }                                                                               \
    __syncthreads();                                                                \
    {                                                                               \
        int r = wm * 16 + (lane >> 2);                                              \
        _Pragma("unroll")                                                           \
        for (int nt = 0; nt < 4; ++nt) {                                            \
            int col = wn * 32 + nt * 8 + kq;                                        \
            *reinterpret_cast<float2*>(smem + (size_t)r * O_STRIDE + col)       = make_float2(c[nt][0], c[nt][1]); \
            *reinterpret_cast<float2*>(smem + (size_t)(r + 8) * O_STRIDE + col) = make_float2(c[nt][2], c[nt][3]); \
        }                                                                           \
    }                                                                               \
    __syncthreads();                                                                \
    {                                                                               \
        const int cb = lane * 4;                                                    \
        const float4 z4 = make_float4(0.f, 0.f, 0.f, 0.f);                          \
        float4 g4 = __ldg(reinterpret_cast<const float4*>(gln + cb));               \
        float4 b4 = __ldg(reinterpret_cast<const float4*>(blnv + cb));              \
        _Pragma("unroll")                                                           \
        for (int it = 0; it < 4; ++it) {                                            \
            int r = wid * 4 + it;                                                   \
            float4 v = *reinterpret_cast<const float4*>(smem + (size_t)r * O_STRIDE + cb); \
            float sum = v.x + v.y + v.z + v.w;                                      \
            float ss  = v.x * v.x + v.y * v.y + v.z * v.z + v.w * v.w;              \
            _Pragma("unroll")                                                       \
            for (int o = 16; o > 0; o >>= 1) {                                      \
                sum += __shfl_xor_sync(0xffffffffu, sum, o);                        \
                ss  += __shfl_xor_sync(0xffffffffu, ss, o);                         \
            }                                                                       \
            float mu = sum * (1.f / 128.f);                                         \
            float rstd = rsqrtf(fmaxf(ss * (1.f / 128.f) - mu * mu, 0.f) + 1e-5f);  \
            if (GUARD) {                                                            \
                int gr = (GR_OUT);                                                  \
                float o0 = fmaxf(fmaf((v.x - mu) * rstd, g4.x, b4.x), 0.f);         \
                float o1 = fmaxf(fmaf((v.y - mu) * rstd, g4.y, b4.y), 0.f);         \
                float o2 = fmaxf(fmaf((v.z - mu) * rstd, g4.z, b4.z), 0.f);         \
                float o3 = fmaxf(fmaf((v.w - mu) * rstd, g4.w, b4.w), 0.f);         \
                *reinterpret_cast<float4*>(out + (size_t)gr * C + cb) = make_float4(o0, o1, o2, o3); \
                *reinterpret_cast<float4*>(aggz + (size_t)gr * C + cb) = z4;        \
            }                                                                       \
        }                                                                           \
    }

// direct: rows row0..row0+63 (launched so all rows valid: 16 CTAs x 64 = 1024 <= M)
__global__ void __launch_bounds__(512, 1) gemm_small(
    const float* __restrict__ agg, const float* __restrict__ xin,
    float* aggz, const uint4* __restrict__ wfrag,
    const float* __restrict__ bias, const float* __restrict__ gln, const float* __restrict__ blnv,
    float* __restrict__ out)
{
    const int row0 = blockIdx.x * MT;
    GEMM_CORE(row0 + (crow & 63), row0 + r, true)
}

// gathered: logical rows from g_ilist[0..g_icount)
__global__ void __launch_bounds__(512, 1) gemm_small_gather(
    const float* __restrict__ agg, const float* __restrict__ xin,
    float* aggz, const uint4* __restrict__ wfrag,
    const float* __restrict__ bias, const float* __restrict__ gln, const float* __restrict__ blnv,
    float* __restrict__ out)
{
    const int cnt = g_icount;
    const int base = blockIdx.x * MT;
    if (base >= cnt) return;
    int sridx = base + (threadIdx.x >> 2 & 63);
    if (sridx > cnt - 1) sridx = cnt - 1;
    const int srow = g_ilist[sridx];
    GEMM_CORE(srow, g_ilist[base + r], (base + r < cnt))
}

// ---------------- head ----------------
__global__ void head_kernel(const float* __restrict__ xu, const float* __restrict__ w,
                            const float* __restrict__ b, float* __restrict__ out) {
    int gid = blockIdx.x * blockDim.x + threadIdx.x;
    int wd = gid >> 5, lane = gid & 31;
    if (wd >= BB) return;
    float4 v  = *reinterpret_cast<const float4*>(xu + (size_t)wd * C + lane * 4);
    float4 ww = *reinterpret_cast<const float4*>(w + lane * 4);
    float s = v.x * ww.x + v.y * ww.y + v.z * ww.z + v.w * ww.w;
#pragma unroll
    for (int o = 16; o > 0; o >>= 1) s += __shfl_xor_sync(0xffffffffu, s, o);
    if (lane == 0) out[wd] = s + b[0];
}

// ---------------- launch: demand-driven dataflow, latency-optimized gemms ----------------
extern "C" void kernel_launch(void* const* d_in, const int* in_sizes, int n_in,
                              void* d_out, int out_size) {
    const float* x_user  = (const float*)d_in[0];
    const float* x_item  = (const float*)d_in[1];
    const int* e_ui_src  = (const int*)d_in[2];
    const int* e_ui_dst  = (const int*)d_in[3];
    const int* e_iu_src  = (const int*)d_in[4];
    const int* e_iu_dst  = (const int*)d_in[5];
    const float* w_rel   = (const float*)d_in[6];
    const float* w_root  = (const float*)d_in[7];
    const float* bias    = (const float*)d_in[8];
    const float* ln_g    = (const float*)d_in[9];
    const float* ln_b    = (const float*)d_in[10];
    const float* lin_w   = (const float*)d_in[11];
    const float* lin_b   = (const float*)d_in[12];
    float* out = (float*)d_out;

    float *xu_a, *xu_b, *xi_a, *aggu, *aggi;
    uint4* wfrag;
    cudaGetSymbolAddress((void**)&xu_a, g_xu_a);
    cudaGetSymbolAddress((void**)&xu_b, g_xu_b);
    cudaGetSymbolAddress((void**)&xi_a, g_xi_a);
    cudaGetSymbolAddress((void**)&aggu, g_agg_u);
    cudaGetSymbolAddress((void**)&aggi, g_agg_i);
    cudaGetSymbolAddress((void**)&wfrag, g_wfrag);

    cudaFuncSetAttribute(gemm_small, cudaFuncAttributeMaxDynamicSharedMemorySize, GEMM_SMEM_BYTES);
    cudaFuncSetAttribute(gemm_small_gather, cudaFuncAttributeMaxDynamicSharedMemorySize, GEMM_SMEM_BYTES);

    cudaStream_t sB = 0;
    cudaEvent_t evC = 0, evU0 = 0;
    bool multi = (cudaStreamCreateWithFlags(&sB, cudaStreamNonBlocking) == cudaSuccess);
    if (multi) multi =
        (cudaEventCreateWithFlags(&evC,  cudaEventDisableTiming) == cudaSuccess) &&
        (cudaEventCreateWithFlags(&evU0, cudaEventDisableTiming) == cudaSuccess);
    cudaStream_t sU = multi ? sB : (cudaStream_t)0;

    const int SBLKB = ((EE / 16) * 32 + 255) / 256;   // bitmap scatter

    // stream0: prep + demand-set construction
    prep_w<<<(4 * 16 * 16 * 32 + 255) / 256, 256>>>(w_rel, w_root, wfrag);
    reset_kernel<<<8, 256>>>();
    compact_kernel<<<(EE / 4 + 255) / 256, 256>>>(e_iu_src, e_iu_dst);
    if (multi) cudaEventRecord(evC, 0);

    // user chain L0 (sU): elist scatter x_item -> aggu[<BB], then 16-CTA gemmU0 -> xu_a
    if (multi) cudaStreamWaitEvent(sU, evC, 0);
    scatter_list_kernel<<<160, 256, 0, sU>>>(x_item, e_iu_src, e_iu_dst, aggu);
    gemm_small<<<NBLK_H, 512, GEMM_SMEM_BYTES, sU>>>(
        aggu, x_user, aggu, wfrag + (size_t)1 * 16 * 16 * 32,
        bias + 1 * C, ln_g + 0 * C, ln_b + 0 * C, xu_a);
    if (multi) cudaEventRecord(evU0, sU);

    // item chain L0 (stream0): bitmap-filtered ui scatter -> gathered gemmI0 -> xi_a
    scatter_bm_kernel<<<SBLKB, 256, 0, 0>>>(x_user, e_ui_src, e_ui_dst, aggi, EE);
    gemm_small_gather<<<NBLK_IG, 512, GEMM_SMEM_BYTES, 0>>>(
        aggi, x_item, aggi, wfrag + (size_t)0 * 16 * 16 * 32,
        bias + 0 * C, ln_g + 1 * C, ln_b + 1 * C, xi_a);

    // layer 1 user side: elist scatter xi_a -> aggu[<BB], then gemmU1 -> xu_b
    if (multi) cudaStreamWaitEvent(0, evU0, 0);
    scatter_list_kernel<<<160, 256, 0, 0>>>(xi_a, e_iu_src, e_iu_dst, aggu);
    gemm_small<<<NBLK_H, 512, GEMM_SMEM_BYTES, 0>>>(
        aggu, xu_a, aggu, wfrag + (size_t)3 * 16 * 16 * 32,
        bias + 3 * C, ln_g + 2 * C, ln_b + 2 * C, xu_b);

    head_kernel<<<(BB * 32 + 255) / 256, 256, 0, 0>>>(xu_b, lin_w, lin_b, out);
}